// round 3
// baseline (speedup 1.0000x reference)
#include <cuda_runtime.h>
#include <math.h>

#define B   8
#define T   2048
#define EMB 1024
#define H   128
#define BT  (B*T)

// Scratch for Q/K/V projections (no cudaMalloc allowed).
__device__ float g_q[BT * H];
__device__ float g_k[BT * H];
__device__ float g_v[BT * H];

// ---------------------------------------------------------------------------
// Projection GEMM: out[16384,128] = x[16384,1024] @ W[1024,128]
// BM=64, BN=128(all), BK=16. 256 threads, 4x8 micro-tile per thread.
// grid = (BT/64, 3) ; blockIdx.y selects Q/K/V weight.
// ---------------------------------------------------------------------------
__global__ __launch_bounds__(256) void proj_kernel(
    const float* __restrict__ x,
    const float* __restrict__ Wq,
    const float* __restrict__ Wk,
    const float* __restrict__ Wv)
{
    __shared__ float xs[16][64];    // transposed: [k][row] -> broadcast reads
    __shared__ float ws[16][128];

    const float* __restrict__ W;
    float* out;
    if (blockIdx.y == 0)      { W = Wq; out = g_q; }
    else if (blockIdx.y == 1) { W = Wk; out = g_k; }
    else                      { W = Wv; out = g_v; }

    const int row0 = blockIdx.x * 64;
    const int tid  = threadIdx.x;
    const int ty   = tid >> 4;      // 0..15 -> 4 output rows
    const int tx   = tid & 15;      // 0..15 -> 8 output cols

    float acc[4][8];
    #pragma unroll
    for (int i = 0; i < 4; i++)
        #pragma unroll
        for (int j = 0; j < 8; j++) acc[i][j] = 0.f;

    const int lr = tid >> 2;        // 0..63 : row for xs load
    const int lk = (tid & 3) * 4;   // 0,4,8,12

    for (int kk = 0; kk < EMB; kk += 16) {
        // Load x tile (64x16) transposed into xs[k][row]
        float4 xv = *(const float4*)&x[(size_t)(row0 + lr) * EMB + kk + lk];
        xs[lk + 0][lr] = xv.x;
        xs[lk + 1][lr] = xv.y;
        xs[lk + 2][lr] = xv.z;
        xs[lk + 3][lr] = xv.w;
        // Load W tile (16x128)
        #pragma unroll
        for (int u = 0; u < 2; u++) {
            int f  = tid * 2 + u;          // 0..511 float4 slots
            int k  = f >> 5;               // 0..15
            int c4 = (f & 31) * 4;         // 0..124
            *(float4*)&ws[k][c4] = *(const float4*)&W[(size_t)(kk + k) * H + c4];
        }
        __syncthreads();

        #pragma unroll
        for (int k = 0; k < 16; k++) {
            float a[4], bb[8];
            #pragma unroll
            for (int i = 0; i < 4; i++) a[i] = xs[k][ty * 4 + i];
            *(float4*)&bb[0] = *(const float4*)&ws[k][tx * 8];
            *(float4*)&bb[4] = *(const float4*)&ws[k][tx * 8 + 4];
            #pragma unroll
            for (int i = 0; i < 4; i++)
                #pragma unroll
                for (int j = 0; j < 8; j++)
                    acc[i][j] += a[i] * bb[j];
        }
        __syncthreads();
    }

    #pragma unroll
    for (int i = 0; i < 4; i++) {
        float* dst = &out[(size_t)(row0 + ty * 4 + i) * H + tx * 8];
        *(float4*)dst       = make_float4(acc[i][0], acc[i][1], acc[i][2], acc[i][3]);
        *(float4*)(dst + 4) = make_float4(acc[i][4], acc[i][5], acc[i][6], acc[i][7]);
    }
}

// ---------------------------------------------------------------------------
// Flash attention: grid (T/64, B), 256 threads (8 warps).
// Warp w owns query rows w*8..w*8+7 (entire row set -> warp-local softmax).
// Per key tile of 64: S = Q K^T (K transposed in smem), online softmax,
// then O += P V (V reuses the K smem buffer).
// ---------------------------------------------------------------------------
#define KT_STRIDE 66
#define SM_BUF_OFF (64 * 128)                      // after Qs
#define SM_S_OFF   (64 * 128 + 128 * KT_STRIDE)    // after BUF
#define SMEM_FLOATS (64 * 128 + 128 * KT_STRIDE + 64 * 64)
#define SMEM_BYTES  (SMEM_FLOATS * 4)

__global__ __launch_bounds__(256, 2) void attn_kernel(float* __restrict__ out)
{
    extern __shared__ float sm[];
    float* Qs  = sm;                 // [64][128], pre-scaled by 1/sqrt(H)
    float* BUF = sm + SM_BUF_OFF;    // Kt [128][66]  OR  V [64][128]
    float* Ss  = sm + SM_S_OFF;      // P tile [64][64]

    const int b    = blockIdx.y;
    const int q0   = blockIdx.x * 64;
    const int tid  = threadIdx.x;
    const int warp = tid >> 5;
    const int lane = tid & 31;
    const float scale = 0.08838834764831845f;   // 1/sqrt(128)

    // Load + pre-scale Q tile
    {
        const float* src = g_q + (size_t)(b * T + q0) * H;
        #pragma unroll
        for (int it = 0; it < 8; it++) {
            int idx = tid + it * 256;       // float4 index into 64x128 tile
            int r   = idx >> 5;
            int c4  = (idx & 31) * 4;
            float4 v = *(const float4*)&src[r * H + c4];
            v.x *= scale; v.y *= scale; v.z *= scale; v.w *= scale;
            *(float4*)&Qs[r * H + c4] = v;
        }
    }

    float o[8][4];
    float m[8], l[8];
    #pragma unroll
    for (int i = 0; i < 8; i++) {
        m[i] = -1e30f; l[i] = 0.f;
        o[i][0] = o[i][1] = o[i][2] = o[i][3] = 0.f;
    }

    const int r0 = warp * 8;

    for (int t = 0; t < T; t += 64) {
        __syncthreads();   // prev PV done before overwriting BUF
        // Load K tile transposed: BUF[k][c] = K[t+c][k]
        {
            const float* ksrc = g_k + (size_t)(b * T + t) * H;
            int c = tid >> 2;
            #pragma unroll
            for (int it = 0; it < 8; it++) {
                int k0 = ((tid & 3) + it * 4) * 4;     // 0..124 step 4
                float4 kv = *(const float4*)&ksrc[c * H + k0];
                BUF[(k0 + 0) * KT_STRIDE + c] = kv.x;
                BUF[(k0 + 1) * KT_STRIDE + c] = kv.y;
                BUF[(k0 + 2) * KT_STRIDE + c] = kv.z;
                BUF[(k0 + 3) * KT_STRIDE + c] = kv.w;
            }
        }
        __syncthreads();

        // S[r0+i][lane*2 + {0,1}]
        float s0[8], s1[8];
        #pragma unroll
        for (int i = 0; i < 8; i++) { s0[i] = 0.f; s1[i] = 0.f; }

        for (int k = 0; k < H; k += 4) {
            float qv[8][4];
            #pragma unroll
            for (int i = 0; i < 8; i++)
                *(float4*)qv[i] = *(const float4*)&Qs[(r0 + i) * H + k];
            #pragma unroll
            for (int k2 = 0; k2 < 4; k2++) {
                float2 kv = *(const float2*)&BUF[(k + k2) * KT_STRIDE + lane * 2];
                #pragma unroll
                for (int i = 0; i < 8; i++) {
                    s0[i] += qv[i][k2] * kv.x;
                    s1[i] += qv[i][k2] * kv.y;
                }
            }
        }
        __syncthreads();   // all K reads done -> BUF reusable for V

        // Online softmax (warp-local: whole rows live in this warp)
        #pragma unroll
        for (int i = 0; i < 8; i++) {
            float mx = fmaxf(s0[i], s1[i]);
            #pragma unroll
            for (int off = 16; off > 0; off >>= 1)
                mx = fmaxf(mx, __shfl_xor_sync(0xffffffffu, mx, off));
            float mnew = fmaxf(m[i], mx);
            float corr = __expf(m[i] - mnew);
            float p0 = __expf(s0[i] - mnew);
            float p1 = __expf(s1[i] - mnew);
            float rs = p0 + p1;
            #pragma unroll
            for (int off = 16; off > 0; off >>= 1)
                rs += __shfl_xor_sync(0xffffffffu, rs, off);
            l[i] = l[i] * corr + rs;
            m[i] = mnew;
            o[i][0] *= corr; o[i][1] *= corr; o[i][2] *= corr; o[i][3] *= corr;
            Ss[(r0 + i) * 64 + lane * 2]     = p0;
            Ss[(r0 + i) * 64 + lane * 2 + 1] = p1;
        }

        // Load V tile into BUF as [64][128]
        {
            const float* vsrc = g_v + (size_t)(b * T + t) * H;
            #pragma unroll
            for (int it = 0; it < 8; it++) {
                int idx = tid + it * 256;
                int r   = idx >> 5;
                int c4  = (idx & 31) * 4;
                *(float4*)&BUF[r * H + c4] = *(const float4*)&vsrc[r * H + c4];
            }
        }
        __syncthreads();

        // O += P V  : o[i][j], cols = lane*4 + j
        for (int k = 0; k < 64; k += 4) {
            float pv[8][4];
            #pragma unroll
            for (int i = 0; i < 8; i++)
                *(float4*)pv[i] = *(const float4*)&Ss[(r0 + i) * 64 + k];
            float vv[4][4];
            #pragma unroll
            for (int k2 = 0; k2 < 4; k2++)
                *(float4*)vv[k2] = *(const float4*)&BUF[(k + k2) * H + lane * 4];
            #pragma unroll
            for (int i = 0; i < 8; i++)
                #pragma unroll
                for (int k2 = 0; k2 < 4; k2++) {
                    o[i][0] += pv[i][k2] * vv[k2][0];
                    o[i][1] += pv[i][k2] * vv[k2][1];
                    o[i][2] += pv[i][k2] * vv[k2][2];
                    o[i][3] += pv[i][k2] * vv[k2][3];
                }
        }
    }

    // Epilogue: normalize and store
    #pragma unroll
    for (int i = 0; i < 8; i++) {
        float inv = 1.f / l[i];
        float4 v = make_float4(o[i][0] * inv, o[i][1] * inv,
                               o[i][2] * inv, o[i][3] * inv);
        *(float4*)&out[((size_t)(b * T) + q0 + r0 + i) * H + lane * 4] = v;
    }
}

// ---------------------------------------------------------------------------
// Inputs (metadata order): x, Wk, Wq, Wv. Output: [8,2048,128] fp32.
// ---------------------------------------------------------------------------
extern "C" void kernel_launch(void* const* d_in, const int* in_sizes, int n_in,
                              void* d_out, int out_size)
{
    const float* x  = (const float*)d_in[0];
    const float* Wk = (const float*)d_in[1];
    const float* Wq = (const float*)d_in[2];
    const float* Wv = (const float*)d_in[3];
    float* out = (float*)d_out;

    cudaFuncSetAttribute(attn_kernel,
                         cudaFuncAttributeMaxDynamicSharedMemorySize, SMEM_BYTES);

    proj_kernel<<<dim3(BT / 64, 3), 256>>>(x, Wq, Wk, Wv);
    attn_kernel<<<dim3(T / 64, B), 256, SMEM_BYTES>>>(out);
}

// round 4
// speedup vs baseline: 5.5565x; 5.5565x over previous
#include <cuda_runtime.h>
#include <stdint.h>
#include <math.h>

#define B   8
#define T   2048
#define EMB 1024
#define H   128
#define BT  (B*T)

// Scratch for Q/K/V projections (no cudaMalloc allowed).
__device__ float g_q[BT * H];
__device__ float g_k[BT * H];
__device__ float g_v[BT * H];

// ---------------------------------------------------------------------------
// Helpers: tf32 convert + m16n8k8 tf32 MMA (fp32 accumulate)
// ---------------------------------------------------------------------------
__device__ __forceinline__ uint32_t f2tf32(float f) {
    uint32_t u;
    asm volatile("cvt.rna.tf32.f32 %0, %1;" : "=r"(u) : "f"(f));
    return u;
}

__device__ __forceinline__ void mma_tf32(
    float& d0, float& d1, float& d2, float& d3,
    uint32_t a0, uint32_t a1, uint32_t a2, uint32_t a3,
    uint32_t b0, uint32_t b1)
{
    asm volatile(
        "mma.sync.aligned.m16n8k8.row.col.f32.tf32.tf32.f32 "
        "{%0,%1,%2,%3}, {%4,%5,%6,%7}, {%8,%9}, {%0,%1,%2,%3};"
        : "+f"(d0), "+f"(d1), "+f"(d2), "+f"(d3)
        : "r"(a0), "r"(a1), "r"(a2), "r"(a3), "r"(b0), "r"(b1));
}

// ---------------------------------------------------------------------------
// Projection GEMM: out[16384,128] = x[16384,1024] @ W[1024,128]
// CTA tile 128x128, BK=32, 256 threads = 8 warps (4 M x 2 N).
// grid = (BT/128, 3); blockIdx.y selects Q/K/V weight.
// smem holds tf32-converted tiles: xs[row][36], ws[k][132].
// ---------------------------------------------------------------------------
__global__ __launch_bounds__(256) void proj_kernel(
    const float* __restrict__ x,
    const float* __restrict__ Wq,
    const float* __restrict__ Wk,
    const float* __restrict__ Wv)
{
    __shared__ uint32_t xs[128 * 36];   // [row][k], pad to 36
    __shared__ uint32_t ws[32 * 132];   // [k][n],   pad to 132

    const float* __restrict__ W;
    float* out;
    if (blockIdx.y == 0)      { W = Wq; out = g_q; }
    else if (blockIdx.y == 1) { W = Wk; out = g_k; }
    else                      { W = Wv; out = g_v; }

    const int row0 = blockIdx.x * 128;
    const int tid  = threadIdx.x;
    const int warp = tid >> 5, lane = tid & 31;
    const int g = lane >> 2, t = lane & 3;          // groupID / tid-in-group
    const int wm = warp >> 1, wn = warp & 1;        // warp tile: 32 rows x 64 cols

    float c[2][8][4];
    #pragma unroll
    for (int i = 0; i < 2; i++)
        #pragma unroll
        for (int j = 0; j < 8; j++)
            c[i][j][0] = c[i][j][1] = c[i][j][2] = c[i][j][3] = 0.f;

    for (int kk = 0; kk < EMB; kk += 32) {
        // x tile 128x32 -> xs (tf32)
        #pragma unroll
        for (int p = 0; p < 4; p++) {
            int idx = tid + p * 256;
            int r = idx >> 3, kq = (idx & 7) * 4;
            float4 v = *(const float4*)&x[(size_t)(row0 + r) * EMB + kk + kq];
            *(uint4*)&xs[r * 36 + kq] =
                make_uint4(f2tf32(v.x), f2tf32(v.y), f2tf32(v.z), f2tf32(v.w));
        }
        // W tile 32x128 -> ws (tf32)
        #pragma unroll
        for (int p = 0; p < 4; p++) {
            int idx = tid + p * 256;
            int r = idx >> 5, n4 = (idx & 31) * 4;
            float4 v = *(const float4*)&W[(size_t)(kk + r) * H + n4];
            *(uint4*)&ws[r * 132 + n4] =
                make_uint4(f2tf32(v.x), f2tf32(v.y), f2tf32(v.z), f2tf32(v.w));
        }
        __syncthreads();

        #pragma unroll
        for (int ks = 0; ks < 4; ks++) {
            const int kb = ks * 8;
            uint32_t a[2][4];
            #pragma unroll
            for (int i = 0; i < 2; i++) {
                int rb = wm * 32 + i * 16;
                a[i][0] = xs[(rb + g) * 36 + kb + t];
                a[i][1] = xs[(rb + g + 8) * 36 + kb + t];
                a[i][2] = xs[(rb + g) * 36 + kb + t + 4];
                a[i][3] = xs[(rb + g + 8) * 36 + kb + t + 4];
            }
            #pragma unroll
            for (int j = 0; j < 8; j++) {
                int nc = wn * 64 + j * 8 + g;
                uint32_t b0 = ws[(kb + t) * 132 + nc];
                uint32_t b1 = ws[(kb + t + 4) * 132 + nc];
                #pragma unroll
                for (int i = 0; i < 2; i++)
                    mma_tf32(c[i][j][0], c[i][j][1], c[i][j][2], c[i][j][3],
                             a[i][0], a[i][1], a[i][2], a[i][3], b0, b1);
            }
        }
        __syncthreads();
    }

    #pragma unroll
    for (int i = 0; i < 2; i++) {
        int r = row0 + wm * 32 + i * 16 + g;
        #pragma unroll
        for (int j = 0; j < 8; j++) {
            int col = wn * 64 + j * 8 + 2 * t;
            *(float2*)&out[(size_t)r * H + col] =
                make_float2(c[i][j][0], c[i][j][1]);
            *(float2*)&out[(size_t)(r + 8) * H + col] =
                make_float2(c[i][j][2], c[i][j][3]);
        }
    }
}

// ---------------------------------------------------------------------------
// Flash attention (tf32 MMA): grid (T/128, B), 256 threads = 8 warps.
// Each warp owns 16 query rows (all softmax state warp-local).
// Q lives in registers as tf32 fragments; K/V tiles (64 keys) in smem.
// P round-trips through smem to convert C-fragment -> A-fragment layout.
// ---------------------------------------------------------------------------
#define VS_OFF (64 * 132)
#define PS_OFF (64 * 132 * 2)
#define SMEM_U32 (64 * 132 * 2 + 128 * 68)
#define ATTN_SMEM_BYTES (SMEM_U32 * 4)

__global__ __launch_bounds__(256, 1) void attn_kernel(float* __restrict__ out)
{
    extern __shared__ uint32_t sm[];
    uint32_t* Ks = sm;              // [64][132] tf32
    uint32_t* Vs = sm + VS_OFF;     // [64][132] tf32
    uint32_t* Ps = sm + PS_OFF;     // [128][68] tf32

    const int b    = blockIdx.y;
    const int q0   = blockIdx.x * 128;
    const int tid  = threadIdx.x;
    const int warp = tid >> 5, lane = tid & 31;
    const int g = lane >> 2, t = lane & 3;
    const int qr0 = warp * 16;
    const float scale = 0.08838834764831845f;   // 1/sqrt(128)

    // Q fragments: 16 ksteps x 4 regs, pre-scaled, reused for all key tiles.
    uint32_t qa[16][4];
    {
        const float* qp = g_q + (size_t)(b * T + q0 + qr0) * H;
        #pragma unroll
        for (int ks = 0; ks < 16; ks++) {
            int col = ks * 8 + t;
            qa[ks][0] = f2tf32(scale * qp[g * H + col]);
            qa[ks][1] = f2tf32(scale * qp[(g + 8) * H + col]);
            qa[ks][2] = f2tf32(scale * qp[g * H + col + 4]);
            qa[ks][3] = f2tf32(scale * qp[(g + 8) * H + col + 4]);
        }
    }

    float o[16][4];
    #pragma unroll
    for (int j = 0; j < 16; j++)
        o[j][0] = o[j][1] = o[j][2] = o[j][3] = 0.f;
    float m0 = -1e30f, m1 = -1e30f, l0 = 0.f, l1 = 0.f;

    for (int t0 = 0; t0 < T; t0 += 64) {
        __syncthreads();   // all warps done reading K/V of previous tile
        {
            const float* kp = g_k + (size_t)(b * T + t0) * H;
            const float* vp = g_v + (size_t)(b * T + t0) * H;
            #pragma unroll
            for (int p = 0; p < 8; p++) {
                int idx = tid + p * 256;
                int r = idx >> 5, c4 = (idx & 31) * 4;
                float4 kv = *(const float4*)&kp[r * H + c4];
                *(uint4*)&Ks[r * 132 + c4] =
                    make_uint4(f2tf32(kv.x), f2tf32(kv.y), f2tf32(kv.z), f2tf32(kv.w));
                float4 vv = *(const float4*)&vp[r * H + c4];
                *(uint4*)&Vs[r * 132 + c4] =
                    make_uint4(f2tf32(vv.x), f2tf32(vv.y), f2tf32(vv.z), f2tf32(vv.w));
            }
        }
        __syncthreads();

        // ---- S = Q K^T : s[j] covers keys j*8 .. j*8+7 ----
        float s[8][4];
        #pragma unroll
        for (int j = 0; j < 8; j++)
            s[j][0] = s[j][1] = s[j][2] = s[j][3] = 0.f;

        #pragma unroll
        for (int ks = 0; ks < 16; ks++) {
            #pragma unroll
            for (int j = 0; j < 8; j++) {
                uint32_t b0 = Ks[(j * 8 + g) * 132 + ks * 8 + t];
                uint32_t b1 = Ks[(j * 8 + g) * 132 + ks * 8 + t + 4];
                mma_tf32(s[j][0], s[j][1], s[j][2], s[j][3],
                         qa[ks][0], qa[ks][1], qa[ks][2], qa[ks][3], b0, b1);
            }
        }

        // ---- online softmax (rows qr0+g and qr0+g+8) ----
        float mx0 = -1e30f, mx1 = -1e30f;
        #pragma unroll
        for (int j = 0; j < 8; j++) {
            mx0 = fmaxf(mx0, fmaxf(s[j][0], s[j][1]));
            mx1 = fmaxf(mx1, fmaxf(s[j][2], s[j][3]));
        }
        #pragma unroll
        for (int off = 1; off <= 2; off <<= 1) {
            mx0 = fmaxf(mx0, __shfl_xor_sync(0xffffffffu, mx0, off));
            mx1 = fmaxf(mx1, __shfl_xor_sync(0xffffffffu, mx1, off));
        }
        float mn0 = fmaxf(m0, mx0), mn1 = fmaxf(m1, mx1);
        float cr0 = __expf(m0 - mn0), cr1 = __expf(m1 - mn1);
        float rs0 = 0.f, rs1 = 0.f;
        #pragma unroll
        for (int j = 0; j < 8; j++) {
            uint32_t u0 = f2tf32(__expf(s[j][0] - mn0));
            uint32_t u1 = f2tf32(__expf(s[j][1] - mn0));
            rs0 += __uint_as_float(u0) + __uint_as_float(u1);
            *(uint2*)&Ps[(qr0 + g) * 68 + j * 8 + 2 * t] = make_uint2(u0, u1);
            uint32_t u2 = f2tf32(__expf(s[j][2] - mn1));
            uint32_t u3 = f2tf32(__expf(s[j][3] - mn1));
            rs1 += __uint_as_float(u2) + __uint_as_float(u3);
            *(uint2*)&Ps[(qr0 + g + 8) * 68 + j * 8 + 2 * t] = make_uint2(u2, u3);
        }
        #pragma unroll
        for (int off = 1; off <= 2; off <<= 1) {
            rs0 += __shfl_xor_sync(0xffffffffu, rs0, off);
            rs1 += __shfl_xor_sync(0xffffffffu, rs1, off);
        }
        l0 = l0 * cr0 + rs0;  m0 = mn0;
        l1 = l1 * cr1 + rs1;  m1 = mn1;
        #pragma unroll
        for (int j = 0; j < 16; j++) {
            o[j][0] *= cr0; o[j][1] *= cr0;
            o[j][2] *= cr1; o[j][3] *= cr1;
        }
        __syncwarp();   // P rows are warp-private: warp-level ordering suffices

        // ---- O += P V ----
        #pragma unroll
        for (int ks = 0; ks < 8; ks++) {
            uint32_t pa0 = Ps[(qr0 + g) * 68 + ks * 8 + t];
            uint32_t pa1 = Ps[(qr0 + g + 8) * 68 + ks * 8 + t];
            uint32_t pa2 = Ps[(qr0 + g) * 68 + ks * 8 + t + 4];
            uint32_t pa3 = Ps[(qr0 + g + 8) * 68 + ks * 8 + t + 4];
            #pragma unroll
            for (int j = 0; j < 16; j++) {
                uint32_t b0 = Vs[(ks * 8 + t) * 132 + j * 8 + g];
                uint32_t b1 = Vs[(ks * 8 + t + 4) * 132 + j * 8 + g];
                mma_tf32(o[j][0], o[j][1], o[j][2], o[j][3],
                         pa0, pa1, pa2, pa3, b0, b1);
            }
        }
    }

    // Epilogue: normalize + store
    float inv0 = 1.f / l0, inv1 = 1.f / l1;
    float* op = out + (size_t)(b * T + q0 + qr0) * H;
    #pragma unroll
    for (int j = 0; j < 16; j++) {
        int col = j * 8 + 2 * t;
        *(float2*)&op[g * H + col] =
            make_float2(o[j][0] * inv0, o[j][1] * inv0);
        *(float2*)&op[(g + 8) * H + col] =
            make_float2(o[j][2] * inv1, o[j][3] * inv1);
    }
}

// ---------------------------------------------------------------------------
// Inputs (metadata order): x, Wk, Wq, Wv. Output: [8,2048,128] fp32.
// ---------------------------------------------------------------------------
extern "C" void kernel_launch(void* const* d_in, const int* in_sizes, int n_in,
                              void* d_out, int out_size)
{
    const float* x  = (const float*)d_in[0];
    const float* Wk = (const float*)d_in[1];
    const float* Wq = (const float*)d_in[2];
    const float* Wv = (const float*)d_in[3];
    float* out = (float*)d_out;

    cudaFuncSetAttribute(attn_kernel,
                         cudaFuncAttributeMaxDynamicSharedMemorySize,
                         ATTN_SMEM_BYTES);

    proj_kernel<<<dim3(BT / 128, 3), 256>>>(x, Wq, Wk, Wv);
    attn_kernel<<<dim3(T / 128, B), 256, ATTN_SMEM_BYTES>>>(out);
}

// round 8
// speedup vs baseline: 5.6362x; 1.0144x over previous
#include <cuda_runtime.h>
#include <stdint.h>
#include <math.h>

#define B   8
#define T   2048
#define EMB 1024
#define H   128
#define BT  (B*T)

// Scratch for Q/K/V projections (no cudaMalloc allowed).
__device__ float g_q[BT * H];
__device__ float g_k[BT * H];
__device__ float g_v[BT * H];

// ---------------------------------------------------------------------------
// Helpers: tf32 convert + m16n8k8 tf32 MMA (fp32 accumulate)
// ---------------------------------------------------------------------------
__device__ __forceinline__ uint32_t f2tf32(float f) {
    uint32_t u;
    asm volatile("cvt.rna.tf32.f32 %0, %1;" : "=r"(u) : "f"(f));
    return u;
}

__device__ __forceinline__ void mma_tf32(
    float& d0, float& d1, float& d2, float& d3,
    uint32_t a0, uint32_t a1, uint32_t a2, uint32_t a3,
    uint32_t b0, uint32_t b1)
{
    asm volatile(
        "mma.sync.aligned.m16n8k8.row.col.f32.tf32.tf32.f32 "
        "{%0,%1,%2,%3}, {%4,%5,%6,%7}, {%8,%9}, {%0,%1,%2,%3};"
        : "+f"(d0), "+f"(d1), "+f"(d2), "+f"(d3)
        : "r"(a0), "r"(a1), "r"(a2), "r"(a3), "r"(b0), "r"(b1));
}

// ---------------------------------------------------------------------------
// Projection GEMM: out[16384,128] = x[16384,1024] @ W[1024,128]
// CTA tile 128x128, BK=32, 256 threads = 8 warps (4 M x 2 N).
// Pair-packed smem (uint2 = {elem k, elem k+4}) -> all fragment loads LDS.64.
// ---------------------------------------------------------------------------
#define XS2_STRIDE 20    // uint2 per row (16 + 4 pad) -> 40 words, mod32 = 8
#define WS2_STRIDE 132   // uint2 per pair-row        -> 264 words, mod32 = 8

__global__ __launch_bounds__(256, 2) void proj_kernel(
    const float* __restrict__ x,
    const float* __restrict__ Wq,
    const float* __restrict__ Wk,
    const float* __restrict__ Wv)
{
    __shared__ uint2 xs2[128 * XS2_STRIDE];   // [row][pair(k,k+4)]
    __shared__ uint2 ws2[16 * WS2_STRIDE];    // [pairrow(k,k+4)][n]

    const float* __restrict__ W;
    float* out;
    if (blockIdx.y == 0)      { W = Wq; out = g_q; }
    else if (blockIdx.y == 1) { W = Wk; out = g_k; }
    else                      { W = Wv; out = g_v; }

    const int row0 = blockIdx.x * 128;
    const int tid  = threadIdx.x;
    const int warp = tid >> 5, lane = tid & 31;
    const int g = lane >> 2, t = lane & 3;
    const int wm = warp >> 1, wn = warp & 1;      // warp tile: 32 rows x 64 cols

    float c[2][8][4];
    #pragma unroll
    for (int i = 0; i < 2; i++)
        #pragma unroll
        for (int j = 0; j < 8; j++)
            c[i][j][0] = c[i][j][1] = c[i][j][2] = c[i][j][3] = 0.f;

    for (int kk = 0; kk < EMB; kk += 32) {
        // x tile 128x32 -> pair-packed tf32
        #pragma unroll
        for (int p = 0; p < 2; p++) {
            int idx = tid + p * 256;             // 0..511
            int r = idx >> 2, ksg = idx & 3;
            const float* src = &x[(size_t)(row0 + r) * EMB + kk + ksg * 8];
            float4 v0 = *(const float4*)src;
            float4 v1 = *(const float4*)(src + 4);
            uint2* dst = &xs2[r * XS2_STRIDE + ksg * 4];
            dst[0] = make_uint2(f2tf32(v0.x), f2tf32(v1.x));
            dst[1] = make_uint2(f2tf32(v0.y), f2tf32(v1.y));
            dst[2] = make_uint2(f2tf32(v0.z), f2tf32(v1.z));
            dst[3] = make_uint2(f2tf32(v0.w), f2tf32(v1.w));
        }
        // W tile 32x128 -> pair-packed tf32
        #pragma unroll
        for (int p = 0; p < 2; p++) {
            int idx = tid + p * 256;
            int pr = idx >> 5, n4 = (idx & 31) * 4;
            int ks = pr >> 2, tt = pr & 3;
            const float* s0 = &W[(size_t)(kk + ks * 8 + tt) * H + n4];
            float4 a = *(const float4*)s0;
            float4 b2 = *(const float4*)(s0 + 4 * H);
            uint2* dst = &ws2[pr * WS2_STRIDE + n4];
            dst[0] = make_uint2(f2tf32(a.x), f2tf32(b2.x));
            dst[1] = make_uint2(f2tf32(a.y), f2tf32(b2.y));
            dst[2] = make_uint2(f2tf32(a.z), f2tf32(b2.z));
            dst[3] = make_uint2(f2tf32(a.w), f2tf32(b2.w));
        }
        __syncthreads();

        #pragma unroll
        for (int ks = 0; ks < 4; ks++) {
            uint2 A[2][2];
            #pragma unroll
            for (int i = 0; i < 2; i++) {
                int rb = wm * 32 + i * 16;
                A[i][0] = xs2[(rb + g) * XS2_STRIDE + ks * 4 + t];
                A[i][1] = xs2[(rb + g + 8) * XS2_STRIDE + ks * 4 + t];
            }
            #pragma unroll
            for (int j = 0; j < 8; j++) {
                uint2 bb = ws2[(ks * 4 + t) * WS2_STRIDE + wn * 64 + j * 8 + g];
                #pragma unroll
                for (int i = 0; i < 2; i++)
                    mma_tf32(c[i][j][0], c[i][j][1], c[i][j][2], c[i][j][3],
                             A[i][0].x, A[i][1].x, A[i][0].y, A[i][1].y,
                             bb.x, bb.y);
            }
        }
        __syncthreads();
    }

    #pragma unroll
    for (int i = 0; i < 2; i++) {
        int r = row0 + wm * 32 + i * 16 + g;
        #pragma unroll
        for (int j = 0; j < 8; j++) {
            int col = wn * 64 + j * 8 + 2 * t;
            *(float2*)&out[(size_t)r * H + col] =
                make_float2(c[i][j][0], c[i][j][1]);
            *(float2*)&out[(size_t)(r + 8) * H + col] =
                make_float2(c[i][j][2], c[i][j][3]);
        }
    }
}

// ---------------------------------------------------------------------------
// Flash attention (tf32 MMA, pair-packed smem): grid (T/128, B), 8 warps.
// Each warp owns 16 query rows. Q in registers (staged via smem),
// K/V pair-packed for LDS.64 B-fragments, P pair-packed for LDS.64 A-frags.
// ---------------------------------------------------------------------------
#define KS2_STRIDE 68    // uint2/key-row: 136 words, mod32=8 -> conflict-free
#define VS2_STRIDE 132   // uint2/pair-row: 264 words, mod32=8
#define PS2_STRIDE 36    // uint2/q-row:    72 words, mod32=8
#define KS2_OFF 0
#define VS2_OFF (64 * KS2_STRIDE)                    // 4352
#define PS2_OFF (VS2_OFF + 32 * VS2_STRIDE)          // 8576
#define ATTN_SMEM_U2 (PS2_OFF + 128 * PS2_STRIDE)    // 13184
#define ATTN_SMEM_BYTES (ATTN_SMEM_U2 * 8)           // 105472
#define QSTAGE_STRIDE 132                            // words per row

__global__ __launch_bounds__(256, 1) void attn_kernel(float* __restrict__ out)
{
    extern __shared__ uint2 sm2[];
    uint2* Ks2 = sm2 + KS2_OFF;      // [64 keys][pair(hd k, k+4)]
    uint2* Vs2 = sm2 + VS2_OFF;      // [pair(key k, k+4)][hd n]
    uint2* Ps2 = sm2 + PS2_OFF;      // [128 q-rows][pair(col, col+4)]
    uint32_t* Psw = (uint32_t*)Ps2;

    const int b    = blockIdx.y;
    const int q0   = blockIdx.x * 128;
    const int tid  = threadIdx.x;
    const int warp = tid >> 5, lane = tid & 31;
    const int g = lane >> 2, t = lane & 3;
    const int qr0 = warp * 16;
    const float scale = 0.08838834764831845f;   // 1/sqrt(128)

    // ---- Stage Q through smem (coalesced), read fragments conflict-free ----
    // 128 rows x 128 cols = 4096 float4 slots -> 16 iterations of 256 threads.
    uint32_t qa[16][4];
    {
        uint32_t* Qst = (uint32_t*)sm2;          // [128][132] tf32 (pre-scaled)
        const float* qsrc = g_q + (size_t)(b * T + q0) * H;
        #pragma unroll
        for (int p = 0; p < 16; p++) {
            int idx = tid + p * 256;             // 0..4095
            int r = idx >> 5, c4 = (idx & 31) * 4;
            float4 v = *(const float4*)&qsrc[r * H + c4];
            uint4 u = make_uint4(f2tf32(v.x * scale), f2tf32(v.y * scale),
                                 f2tf32(v.z * scale), f2tf32(v.w * scale));
            *(uint4*)&Qst[r * QSTAGE_STRIDE + c4] = u;
        }
        __syncthreads();
        #pragma unroll
        for (int ks = 0; ks < 16; ks++) {
            int col = ks * 8 + t;
            qa[ks][0] = Qst[(qr0 + g) * QSTAGE_STRIDE + col];
            qa[ks][1] = Qst[(qr0 + g + 8) * QSTAGE_STRIDE + col];
            qa[ks][2] = Qst[(qr0 + g) * QSTAGE_STRIDE + col + 4];
            qa[ks][3] = Qst[(qr0 + g + 8) * QSTAGE_STRIDE + col + 4];
        }
    }

    float o[16][4];
    #pragma unroll
    for (int j = 0; j < 16; j++)
        o[j][0] = o[j][1] = o[j][2] = o[j][3] = 0.f;
    float m0 = -1e30f, m1 = -1e30f, l0 = 0.f, l1 = 0.f;

    // P scatter-write word offsets (pair-packed A layout)
    const int poff0 = (t & 1) * 4 + (t >> 1);        // local col 2t
    // local col 2t+1 -> poff0 + 2

    for (int t0 = 0; t0 < T; t0 += 64) {
        __syncthreads();   // prev tile reads done (also covers Q-stage reads)
        {
            const float* kp = g_k + (size_t)(b * T + t0) * H;
            const float* vp = g_v + (size_t)(b * T + t0) * H;
            // K: 64 keys x 16 hd-groups -> Ks2[key][ksg*4 + 0..3]
            #pragma unroll
            for (int p = 0; p < 4; p++) {
                int idx = tid + p * 256;
                int r = idx >> 4, ksg = idx & 15;
                const float* src = kp + r * H + ksg * 8;
                float4 v0 = *(const float4*)src;
                float4 v1 = *(const float4*)(src + 4);
                uint2* dst = &Ks2[r * KS2_STRIDE + ksg * 4];
                dst[0] = make_uint2(f2tf32(v0.x), f2tf32(v1.x));
                dst[1] = make_uint2(f2tf32(v0.y), f2tf32(v1.y));
                dst[2] = make_uint2(f2tf32(v0.z), f2tf32(v1.z));
                dst[3] = make_uint2(f2tf32(v0.w), f2tf32(v1.w));
            }
            // V: 32 pair-rows x 32 n-groups -> Vs2[pr][n4 + 0..3]
            #pragma unroll
            for (int p = 0; p < 4; p++) {
                int idx = tid + p * 256;
                int pr = idx >> 5, n4 = (idx & 31) * 4;
                int ks = pr >> 2, tt = pr & 3;
                const float* s0 = vp + (ks * 8 + tt) * H + n4;
                float4 a = *(const float4*)s0;
                float4 c2 = *(const float4*)(s0 + 4 * H);
                uint2* dst = &Vs2[pr * VS2_STRIDE + n4];
                dst[0] = make_uint2(f2tf32(a.x), f2tf32(c2.x));
                dst[1] = make_uint2(f2tf32(a.y), f2tf32(c2.y));
                dst[2] = make_uint2(f2tf32(a.z), f2tf32(c2.z));
                dst[3] = make_uint2(f2tf32(a.w), f2tf32(c2.w));
            }
        }
        __syncthreads();

        // ---- S = Q K^T ----
        float s[8][4];
        #pragma unroll
        for (int j = 0; j < 8; j++)
            s[j][0] = s[j][1] = s[j][2] = s[j][3] = 0.f;

        #pragma unroll
        for (int ks = 0; ks < 16; ks++) {
            #pragma unroll
            for (int j = 0; j < 8; j++) {
                uint2 kb = Ks2[(j * 8 + g) * KS2_STRIDE + ks * 4 + t];
                mma_tf32(s[j][0], s[j][1], s[j][2], s[j][3],
                         qa[ks][0], qa[ks][1], qa[ks][2], qa[ks][3],
                         kb.x, kb.y);
            }
        }

        // ---- online softmax (rows qr0+g and qr0+g+8) ----
        float mx0 = -1e30f, mx1 = -1e30f;
        #pragma unroll
        for (int j = 0; j < 8; j++) {
            mx0 = fmaxf(mx0, fmaxf(s[j][0], s[j][1]));
            mx1 = fmaxf(mx1, fmaxf(s[j][2], s[j][3]));
        }
        #pragma unroll
        for (int off = 1; off <= 2; off <<= 1) {
            mx0 = fmaxf(mx0, __shfl_xor_sync(0xffffffffu, mx0, off));
            mx1 = fmaxf(mx1, __shfl_xor_sync(0xffffffffu, mx1, off));
        }
        float mn0 = fmaxf(m0, mx0), mn1 = fmaxf(m1, mx1);
        float cr0 = __expf(m0 - mn0), cr1 = __expf(m1 - mn1);
        float rs0 = 0.f, rs1 = 0.f;
        #pragma unroll
        for (int j = 0; j < 8; j++) {
            uint32_t u0 = f2tf32(__expf(s[j][0] - mn0));
            uint32_t u1 = f2tf32(__expf(s[j][1] - mn0));
            uint32_t u2 = f2tf32(__expf(s[j][2] - mn1));
            uint32_t u3 = f2tf32(__expf(s[j][3] - mn1));
            rs0 += __uint_as_float(u0) + __uint_as_float(u1);
            rs1 += __uint_as_float(u2) + __uint_as_float(u3);
            int base_g  = (qr0 + g) * (PS2_STRIDE * 2) + j * 8;
            int base_g8 = (qr0 + g + 8) * (PS2_STRIDE * 2) + j * 8;
            Psw[base_g  + poff0]     = u0;
            Psw[base_g  + poff0 + 2] = u1;
            Psw[base_g8 + poff0]     = u2;
            Psw[base_g8 + poff0 + 2] = u3;
        }
        #pragma unroll
        for (int off = 1; off <= 2; off <<= 1) {
            rs0 += __shfl_xor_sync(0xffffffffu, rs0, off);
            rs1 += __shfl_xor_sync(0xffffffffu, rs1, off);
        }
        l0 = l0 * cr0 + rs0;  m0 = mn0;
        l1 = l1 * cr1 + rs1;  m1 = mn1;
        #pragma unroll
        for (int j = 0; j < 16; j++) {
            o[j][0] *= cr0; o[j][1] *= cr0;
            o[j][2] *= cr1; o[j][3] *= cr1;
        }
        __syncwarp();   // P rows warp-private

        // ---- O += P V ----
        #pragma unroll
        for (int ks = 0; ks < 8; ks++) {
            uint2 pg  = Ps2[(qr0 + g) * PS2_STRIDE + ks * 4 + t];
            uint2 pg8 = Ps2[(qr0 + g + 8) * PS2_STRIDE + ks * 4 + t];
            #pragma unroll
            for (int j = 0; j < 16; j++) {
                uint2 vb = Vs2[(ks * 4 + t) * VS2_STRIDE + j * 8 + g];
                mma_tf32(o[j][0], o[j][1], o[j][2], o[j][3],
                         pg.x, pg8.x, pg.y, pg8.y, vb.x, vb.y);
            }
        }
    }

    // Epilogue: normalize + store
    float inv0 = 1.f / l0, inv1 = 1.f / l1;
    float* op = out + (size_t)(b * T + q0) * H;
    #pragma unroll
    for (int j = 0; j < 16; j++) {
        int col = j * 8 + 2 * t;
        *(float2*)&op[(qr0 + g) * H + col] =
            make_float2(o[j][0] * inv0, o[j][1] * inv0);
        *(float2*)&op[(qr0 + g + 8) * H + col] =
            make_float2(o[j][2] * inv1, o[j][3] * inv1);
    }
}

// ---------------------------------------------------------------------------
// Inputs (metadata order): x, Wk, Wq, Wv. Output: [8,2048,128] fp32.
// ---------------------------------------------------------------------------
extern "C" void kernel_launch(void* const* d_in, const int* in_sizes, int n_in,
                              void* d_out, int out_size)
{
    const float* x  = (const float*)d_in[0];
    const float* Wk = (const float*)d_in[1];
    const float* Wq = (const float*)d_in[2];
    const float* Wv = (const float*)d_in[3];
    float* out = (float*)d_out;

    cudaFuncSetAttribute(attn_kernel,
                         cudaFuncAttributeMaxDynamicSharedMemorySize,
                         ATTN_SMEM_BYTES);

    proj_kernel<<<dim3(BT / 128, 3), 256>>>(x, Wq, Wk, Wv);
    attn_kernel<<<dim3(T / 128, B), 256, ATTN_SMEM_BYTES>>>(out);
}